// round 7
// baseline (speedup 1.0000x reference)
#include <cuda_runtime.h>
#include <cuda_bf16.h>
#include <cstdint>

#define BQ 4096
#define DD 256
#define KK 65536
#define TM 128
#define TN 128
#define NCHUNK 512
#define NMTILE 32
#define MAIN_GRID 148
#define NTHREADS 512
#define MARGIN 8.0f
#define CAND_CAP (1u << 22)

#define APITCH_B 528                    // row pitch bytes (256 bf16 + 8 pad)
#define ABYTES (128 * APITCH_B)         // 67584
#define SM_A   0
#define SM_B0  ABYTES
#define SM_B1  (2 * ABYTES)
#define SMEM_TOTAL (3 * ABYTES)         // 202752

__device__ __nv_bfloat16 g_cent16[(size_t)KK * DD];
__device__ __nv_bfloat16 g_x16[(size_t)BQ * DD];
__device__ float              g_csq[KK];
__device__ unsigned long long g_packed[BQ];
__device__ unsigned long long g_final[BQ];
__device__ unsigned           g_ncand;
__device__ unsigned           g_cand[CAND_CAP];

__device__ __forceinline__ unsigned fkey(float f) {
    unsigned u = __float_as_uint(f);
    return (u & 0x80000000u) ? ~u : (u | 0x80000000u);
}
__device__ __forceinline__ float unfkey(unsigned k) {
    unsigned u = (k & 0x80000000u) ? (k ^ 0x80000000u) : ~k;
    return __uint_as_float(u);
}
__device__ __forceinline__ unsigned smem_u32(const void* p) {
    unsigned a;
    asm("{ .reg .u64 t; cvta.to.shared.u64 t, %1; cvt.u32.u64 %0, t; }"
        : "=r"(a) : "l"(p));
    return a;
}
__device__ __forceinline__ void ldsm_x4(unsigned* r, unsigned addr) {
    asm volatile("ldmatrix.sync.aligned.m8n8.x4.shared.b16 {%0,%1,%2,%3},[%4];"
                 : "=r"(r[0]), "=r"(r[1]), "=r"(r[2]), "=r"(r[3]) : "r"(addr));
}
__device__ __forceinline__ void mma_bf16(float* c, const unsigned* a,
                                         const unsigned* b) {
    asm volatile(
        "mma.sync.aligned.m16n8k16.row.col.f32.bf16.bf16.f32 "
        "{%0,%1,%2,%3},{%4,%5,%6,%7},{%8,%9},{%0,%1,%2,%3};"
        : "+f"(c[0]), "+f"(c[1]), "+f"(c[2]), "+f"(c[3])
        : "r"(a[0]), "r"(a[1]), "r"(a[2]), "r"(a[3]), "r"(b[0]), "r"(b[1]));
}
__device__ __forceinline__ unsigned bfma2(unsigned a, unsigned b, unsigned c) {
    unsigned d;
    asm("fma.rn.bf16x2 %0,%1,%2,%3;" : "=r"(d) : "r"(a), "r"(b), "r"(c));
    return d;
}
__device__ __forceinline__ unsigned long long
wmin3(unsigned long long p, int o1, int o2, int o3) {
    unsigned long long q;
    q = __shfl_xor_sync(0xffffffffu, p, o1); if (q < p) p = q;
    q = __shfl_xor_sync(0xffffffffu, p, o2); if (q < p) p = q;
    if (o3) { q = __shfl_xor_sync(0xffffffffu, p, o3); if (q < p) p = q; }
    return p;
}

// ---------------------------------------------------------------------------
__global__ void init_kernel() {
    int i = blockIdx.x * blockDim.x + threadIdx.x;
    if (i < BQ) {
        g_packed[i] = 0xFFFFFFFFFFFFFFFFull;
        g_final[i]  = 0xFFFFFFFFFFFFFFFFull;
    }
    if (i == 0) g_ncand = 0u;
}
__global__ void pad_kernel() {       // aligns main_kernel with ncu -s 5
    if (blockIdx.x == 0 && threadIdx.x == 0) g_ncand = 0u;
}
__global__ void csq_kernel(const float* __restrict__ cent) {
    int warp = threadIdx.x >> 5, lane = threadIdx.x & 31;
    int c = blockIdx.x * 8 + warp;
    const float4* p = (const float4*)(cent + (size_t)c * DD);
    float s = 0.f;
#pragma unroll
    for (int i = 0; i < 2; i++) {
        float4 v = p[lane + 32 * i];
        s = fmaf(v.x, v.x, s); s = fmaf(v.y, v.y, s);
        s = fmaf(v.z, v.z, s); s = fmaf(v.w, v.w, s);
    }
#pragma unroll
    for (int o = 16; o > 0; o >>= 1) s += __shfl_xor_sync(0xffffffffu, s, o);
    if (lane == 0) g_csq[c] = s;
}
__global__ void cvt_cent_kernel(const float* __restrict__ cent) {
    size_t i = (size_t)blockIdx.x * blockDim.x + threadIdx.x;
    float4 v = ((const float4*)cent)[i];
    ((__nv_bfloat162*)g_cent16)[2 * i]     = __floats2bfloat162_rn(v.x, v.y);
    ((__nv_bfloat162*)g_cent16)[2 * i + 1] = __floats2bfloat162_rn(v.z, v.w);
}
__global__ void cvt_x_kernel(const float* __restrict__ x) {
    size_t i = (size_t)blockIdx.x * blockDim.x + threadIdx.x;
    float4 v = ((const float4*)x)[i];
    ((__nv_bfloat162*)g_x16)[2 * i]     = __floats2bfloat162_rn(v.x, v.y);
    ((__nv_bfloat162*)g_x16)[2 * i + 1] = __floats2bfloat162_rn(v.z, v.w);
}

// ---------------------------------------------------------------------------
__device__ __forceinline__ void load_B_async(unsigned bb, int chunk, int tid) {
    const char* src = (const char*)(g_cent16 + (size_t)chunk * TN * DD);
#pragma unroll
    for (int i = 0; i < 8; i++) {
        int j = i * NTHREADS + tid;      // 4096 x 16B
        int col = j >> 5, seg = j & 31;
        unsigned dst = bb + (unsigned)col * APITCH_B + (unsigned)seg * 16u;
        const void* gp = src + (size_t)col * 512 + seg * 16;
        asm volatile("cp.async.cg.shared.global [%0], [%1], 16;"
                     :: "r"(dst), "l"(gp));
    }
}
__device__ __forceinline__ void load_A(char* smem, int mtile, int tid) {
    const char* src = (const char*)(g_x16 + (size_t)mtile * TM * DD);
#pragma unroll
    for (int i = 0; i < 8; i++) {
        int j = i * NTHREADS + tid;
        int row = j >> 5, seg = j & 31;
        uint4 v = *(const uint4*)(src + (size_t)row * 512 + seg * 16);
        *(uint4*)(smem + SM_A + row * APITCH_B + seg * 16) = v;
    }
}

// ---------------------------------------------------------------------------
__global__ void __launch_bounds__(NTHREADS, 1) main_kernel() {
    extern __shared__ char smem[];
    const unsigned sbase = smem_u32(smem);
    const int tid = threadIdx.x;
    const int wid = tid >> 5, lane = tid & 31;
    const bool isF = wid >= 8;           // fp (HFMA2) role

    const long total = (long)NMTILE * NCHUNK;
    const long s = (long)blockIdx.x * total / MAIN_GRID;
    const long e = (long)(blockIdx.x + 1) * total / MAIN_GRID;
    const int T = (int)(e - s);

    // HMMA role geometry: warp w covers rows [16w,16w+16), cols 0-63
    unsigned aAddr = sbase + SM_A +
        (unsigned)(((wid & 7) * 16 + (lane & 15)) * APITCH_B + (lane >> 4) * 16);
    unsigned bOfs[4];
#pragma unroll
    for (int pr = 0; pr < 4; pr++) {
        int col = pr * 16 + ((lane >> 4) << 3) + (lane & 7);
        bOfs[pr] = (unsigned)(col * APITCH_B + ((lane >> 3) & 1) * 16);
    }
    // FP role geometry: warp v covers rows [16v,16v+16), cols 64-127
    const int v  = wid - 8;
    const int tr = lane >> 3, tc = lane & 7;   // thread: rows 16v+4tr+., cols 64+8j+tc

    float bestH[2]; int bestHI[2]; float snapH[2];
    float bestF[4]; int bestFI[4]; float snapF[4];
#pragma unroll
    for (int r = 0; r < 2; r++) { bestH[r] = 3.4e38f; bestHI[r] = 0; }
#pragma unroll
    for (int r = 0; r < 4; r++) { bestF[r] = 3.4e38f; bestFI[r] = 0; }

    int cur_m = (int)(s >> 9);
    load_A(smem, cur_m, tid);
    if (!isF) {
#pragma unroll
        for (int r = 0; r < 2; r++) {
            unsigned sk = (unsigned)(g_packed[cur_m * TM + (wid & 7) * 16 +
                                             r * 8 + (lane >> 2)] >> 32);
            snapH[r] = (sk == 0xFFFFFFFFu) ? 3.4e38f : unfkey(sk);
        }
    } else {
#pragma unroll
        for (int r = 0; r < 4; r++) {
            unsigned sk = (unsigned)(g_packed[cur_m * TM + v * 16 +
                                             tr * 4 + r] >> 32);
            snapF[r] = (sk == 0xFFFFFFFFu) ? 3.4e38f : unfkey(sk);
        }
    }
    load_B_async(sbase + SM_B0, (int)(s & 511), tid);
    asm volatile("cp.async.commit_group;" ::: "memory");

    for (int i = 0; i < T; i++) {
        const long u = s + i;
        const int mt = (int)(u >> 9);
        const int chunk = (int)(u & 511);
        const unsigned bbase = sbase + (unsigned)((i & 1) ? SM_B1 : SM_B0);

        __syncthreads();
        if (mt != cur_m) {
            if (!isF) {
#pragma unroll
                for (int r = 0; r < 2; r++) {
                    unsigned long long p =
                        ((unsigned long long)fkey(bestH[r]) << 32) |
                        (unsigned)bestHI[r];
                    if ((lane & 3) == 0)
                        atomicMin(&g_packed[cur_m * TM + (wid & 7) * 16 +
                                            r * 8 + (lane >> 2)], p);
                    bestH[r] = 3.4e38f; bestHI[r] = 0;
                }
            } else {
#pragma unroll
                for (int r = 0; r < 4; r++) {
                    unsigned long long p =
                        ((unsigned long long)fkey(bestF[r]) << 32) |
                        (unsigned)bestFI[r];
                    if (tc == 0)
                        atomicMin(&g_packed[cur_m * TM + v * 16 + tr * 4 + r], p);
                    bestF[r] = 3.4e38f; bestFI[r] = 0;
                }
            }
            load_A(smem, mt, tid);
            if (!isF) {
#pragma unroll
                for (int r = 0; r < 2; r++) {
                    unsigned sk = (unsigned)(g_packed[mt * TM + (wid & 7) * 16 +
                                                     r * 8 + (lane >> 2)] >> 32);
                    snapH[r] = (sk == 0xFFFFFFFFu) ? 3.4e38f : unfkey(sk);
                }
            } else {
#pragma unroll
                for (int r = 0; r < 4; r++) {
                    unsigned sk = (unsigned)(g_packed[mt * TM + v * 16 +
                                                     tr * 4 + r] >> 32);
                    snapF[r] = (sk == 0xFFFFFFFFu) ? 3.4e38f : unfkey(sk);
                }
            }
            cur_m = mt;
        }
        if (i + 1 < T) {
            load_B_async(sbase + (unsigned)(((i + 1) & 1) ? SM_B1 : SM_B0),
                         (int)((u + 1) & 511), tid);
            asm volatile("cp.async.commit_group;" ::: "memory");
            asm volatile("cp.async.wait_group 1;" ::: "memory");
        } else {
            asm volatile("cp.async.wait_group 0;" ::: "memory");
        }
        __syncthreads();

        if (!isF) {
            // ================= HMMA path: rows 16w..+16, cols 0-63 ==========
            float acc[8][4];
#pragma unroll
            for (int nf = 0; nf < 8; nf++)
#pragma unroll
                for (int c = 0; c < 4; c++) acc[nf][c] = 0.f;
#pragma unroll
            for (int k16 = 0; k16 < 16; k16++) {
                unsigned a[4], b[4][4];
                ldsm_x4(a, aAddr + (unsigned)(k16 * 32));
#pragma unroll
                for (int pr = 0; pr < 4; pr++)
                    ldsm_x4(b[pr], bbase + bOfs[pr] + (unsigned)(k16 * 32));
#pragma unroll
                for (int pr = 0; pr < 4; pr++) {
                    mma_bf16(acc[pr * 2],     a, &b[pr][0]);
                    mma_bf16(acc[pr * 2 + 1], a, &b[pr][2]);
                }
            }
            const int col0 = chunk * TN + 2 * (lane & 3);
            float q[8][2];
#pragma unroll
            for (int nf = 0; nf < 8; nf++) {
                q[nf][0] = __ldg(&g_csq[col0 + nf * 8]);
                q[nf][1] = __ldg(&g_csq[col0 + nf * 8 + 1]);
            }
#pragma unroll
            for (int half = 0; half < 2; half++) {
                float bv = bestH[half]; int bi = bestHI[half];
#pragma unroll
                for (int nf = 0; nf < 8; nf++)
#pragma unroll
                    for (int cc = 0; cc < 2; cc++) {
                        float d = fmaf(-2.0f, acc[nf][half * 2 + cc], q[nf][cc]);
                        acc[nf][half * 2 + cc] = d;
                        if (d < bv) { bv = d; bi = col0 + nf * 8 + cc; }
                    }
                unsigned long long p =
                    wmin3(((unsigned long long)fkey(bv) << 32) | (unsigned)bi,
                          1, 2, 0);
                bestH[half] = unfkey((unsigned)(p >> 32));
                bestHI[half] = (int)(unsigned)(p & 0xFFFFFFFFu);
            }
            float bnd[2];
            bool any = false;
#pragma unroll
            for (int half = 0; half < 2; half++) {
                bnd[half] = fminf(snapH[half], bestH[half]) + MARGIN;
#pragma unroll
                for (int nf = 0; nf < 8; nf++)
#pragma unroll
                    for (int cc = 0; cc < 2; cc++)
                        any |= (acc[nf][half * 2 + cc] <= bnd[half]);
            }
            if (__any_sync(0xffffffffu, any)) {
#pragma unroll
                for (int half = 0; half < 2; half++) {
                    int row_g = cur_m * TM + (wid & 7) * 16 + half * 8 + (lane >> 2);
#pragma unroll
                    for (int nf = 0; nf < 8; nf++)
#pragma unroll
                        for (int cc = 0; cc < 2; cc++)
                            if (acc[nf][half * 2 + cc] <= bnd[half]) {
                                unsigned slot = atomicAdd(&g_ncand, 1u);
                                if (slot < CAND_CAP)
                                    g_cand[slot] = ((unsigned)row_g << 16) |
                                                   (unsigned)(col0 + nf * 8 + cc);
                            }
                }
            }
        } else {
            // ================= HFMA2 path: rows 16v..+16, cols 64-127 =======
            unsigned acc2[32];
#pragma unroll
            for (int k = 0; k < 32; k++) acc2[k] = 0u;
            const unsigned aB = sbase + SM_A +
                                (unsigned)((v * 16 + tr * 4) * APITCH_B);
            const unsigned bB = bbase + (unsigned)((64 + tc) * APITCH_B);
#pragma unroll 4
            for (int blk = 0; blk < 64; blk++) {       // 2 k-pairs per block
                uint2 av[4], bv[8];
#pragma unroll
                for (int r = 0; r < 4; r++)
                    av[r] = *(const uint2*)(smem + (aB - sbase) +
                                            r * APITCH_B + blk * 8);
#pragma unroll
                for (int j = 0; j < 8; j++)
                    bv[j] = *(const uint2*)(smem + (bB - sbase) +
                                            j * 8 * APITCH_B + blk * 8);
#pragma unroll
                for (int r = 0; r < 4; r++)
#pragma unroll
                    for (int j = 0; j < 8; j++) {
                        unsigned t = bfma2(av[r].x, bv[j].x, acc2[r * 8 + j]);
                        acc2[r * 8 + j] = bfma2(av[r].y, bv[j].y, t);
                    }
            }
            const int colg0 = chunk * TN + 64 + tc;
            float qf[8];
#pragma unroll
            for (int j = 0; j < 8; j++) qf[j] = __ldg(&g_csq[colg0 + 8 * j]);
#pragma unroll
            for (int r = 0; r < 4; r++) {
                float bv2 = bestF[r]; int bi = bestFI[r];
#pragma unroll
                for (int j = 0; j < 8; j++) {
                    unsigned a = acc2[r * 8 + j];
                    float dot = __uint_as_float(a << 16) +
                                __uint_as_float(a & 0xFFFF0000u);
                    float d = fmaf(-2.0f, dot, qf[j]);
                    acc2[r * 8 + j] = __float_as_uint(d);
                    if (d < bv2) { bv2 = d; bi = colg0 + 8 * j; }
                }
                unsigned long long p =
                    wmin3(((unsigned long long)fkey(bv2) << 32) | (unsigned)bi,
                          1, 2, 4);
                bestF[r] = unfkey((unsigned)(p >> 32));
                bestFI[r] = (int)(unsigned)(p & 0xFFFFFFFFu);
            }
            float bnd[4];
            bool any = false;
#pragma unroll
            for (int r = 0; r < 4; r++) {
                bnd[r] = fminf(snapF[r], bestF[r]) + MARGIN;
#pragma unroll
                for (int j = 0; j < 8; j++)
                    any |= (__uint_as_float(acc2[r * 8 + j]) <= bnd[r]);
            }
            if (__any_sync(0xffffffffu, any)) {
#pragma unroll
                for (int r = 0; r < 4; r++) {
                    int row_g = cur_m * TM + v * 16 + tr * 4 + r;
#pragma unroll
                    for (int j = 0; j < 8; j++)
                        if (__uint_as_float(acc2[r * 8 + j]) <= bnd[r]) {
                            unsigned slot = atomicAdd(&g_ncand, 1u);
                            if (slot < CAND_CAP)
                                g_cand[slot] = ((unsigned)row_g << 16) |
                                               (unsigned)(colg0 + 8 * j);
                        }
                }
            }
        }
    }
    // final flush
    if (!isF) {
#pragma unroll
        for (int r = 0; r < 2; r++) {
            unsigned long long p =
                ((unsigned long long)fkey(bestH[r]) << 32) | (unsigned)bestHI[r];
            if ((lane & 3) == 0)
                atomicMin(&g_packed[cur_m * TM + (wid & 7) * 16 +
                                    r * 8 + (lane >> 2)], p);
        }
    } else {
#pragma unroll
        for (int r = 0; r < 4; r++) {
            unsigned long long p =
                ((unsigned long long)fkey(bestF[r]) << 32) | (unsigned)bestFI[r];
            if (tc == 0)
                atomicMin(&g_packed[cur_m * TM + v * 16 + tr * 4 + r], p);
        }
    }
}

// ---------------------------------------------------------------------------
__global__ void rescore_kernel(const float* __restrict__ x,
                               const float* __restrict__ cent) {
    unsigned n = g_ncand;
    if (n > CAND_CAP) n = CAND_CAP;
    int gw = (blockIdx.x * blockDim.x + threadIdx.x) >> 5;
    int lane = threadIdx.x & 31;
    int nw = (gridDim.x * blockDim.x) >> 5;
    for (unsigned eidx = gw; eidx < n; eidx += nw) {
        unsigned ent = g_cand[eidx];
        unsigned row = ent >> 16;
        unsigned col = ent & 0xFFFFu;
        const float4* xp = (const float4*)(x + (size_t)row * DD);
        const float4* cp = (const float4*)(cent + (size_t)col * DD);
        float sdot = 0.f;
#pragma unroll
        for (int i = 0; i < 2; i++) {
            float4 a = xp[lane + 32 * i];
            float4 b = cp[lane + 32 * i];
            sdot = fmaf(a.x, b.x, sdot); sdot = fmaf(a.y, b.y, sdot);
            sdot = fmaf(a.z, b.z, sdot); sdot = fmaf(a.w, b.w, sdot);
        }
#pragma unroll
        for (int o = 16; o > 0; o >>= 1)
            sdot += __shfl_xor_sync(0xffffffffu, sdot, o);
        if (lane == 0) {
            float dist = fmaf(-2.0f, sdot, __ldg(&g_csq[col]));
            atomicMin(&g_final[row],
                      ((unsigned long long)fkey(dist) << 32) | col);
        }
    }
}

__global__ void finalize_kernel(const float* __restrict__ cent,
                                float* __restrict__ out_xhat,
                                float* __restrict__ out_codes) {
    int warp = threadIdx.x >> 5, lane = threadIdx.x & 31;
    int row = blockIdx.x * 8 + warp;
    if (row >= BQ) return;
    unsigned idx = (unsigned)(g_final[row] & 0xFFFFFFFFull);
    if (out_xhat) {
        const float4* src = (const float4*)(cent + (size_t)idx * DD);
        float4* dst = (float4*)(out_xhat + (size_t)row * DD);
        dst[lane] = src[lane];
        dst[lane + 32] = src[lane + 32];
    }
    if (out_codes && lane == 0) out_codes[row] = (float)idx;
}

// ---------------------------------------------------------------------------
extern "C" void kernel_launch(void* const* d_in, const int* in_sizes, int n_in,
                              void* d_out, int out_size) {
    const float* x = (const float*)d_in[1];
    const float* cent = (const float*)d_in[2];

    float* out = (float*)d_out;
    float* out_xhat = nullptr;
    float* out_codes = nullptr;
    const int XH = BQ * DD;
    if (out_size >= XH) {
        out_xhat = out;
        if (out_size >= XH + BQ) out_codes = out + XH;
    } else if (out_size >= BQ) {
        out_codes = out;
    }

    cudaFuncSetAttribute(main_kernel,
                         cudaFuncAttributeMaxDynamicSharedMemorySize, SMEM_TOTAL);

    init_kernel<<<(BQ + 255) / 256, 256>>>();
    csq_kernel<<<KK / 8, 256>>>(cent);
    cvt_cent_kernel<<<(KK * DD / 4) / 256, 256>>>(cent);
    cvt_x_kernel<<<(BQ * DD / 4) / 256, 256>>>(x);
    pad_kernel<<<1, 32>>>();
    main_kernel<<<MAIN_GRID, NTHREADS, SMEM_TOTAL>>>();
    rescore_kernel<<<512, 256>>>(x, cent);
    finalize_kernel<<<BQ / 8, 256>>>(cent, out_xhat, out_codes);
}

// round 9
// speedup vs baseline: 1.2264x; 1.2264x over previous
#include <cuda_runtime.h>
#include <cuda_bf16.h>
#include <cstdint>

#define BQ 4096
#define DD 256
#define KK 65536
#define TM 128
#define TN 128
#define NCHUNK 512          // KK / TN
#define NMTILE 32           // BQ / TM
#define MAIN_GRID 148
#define NTHREADS 256
#define MARGIN 1.0f
#define CAND_CAP (1u << 22)

#define APITCH 264                      // padded row pitch in bf16 (528 B)
#define ABYTES (128 * APITCH * 2)       // 67584
#define SM_A   0
#define SM_B0  ABYTES
#define SM_B1  (2 * ABYTES)
#define SMEM_TOTAL (3 * ABYTES)         // 202752 bytes

__device__ __nv_bfloat16 g_cent16[(size_t)KK * DD];   // 32 MB
__device__ __nv_bfloat16 g_x16[(size_t)BQ * DD];      // 2 MB
__device__ float              g_csq[KK];
__device__ unsigned long long g_packed[BQ];           // screened best (fkey<<32)|idx
__device__ unsigned long long g_final[BQ];            // exact best among candidates
__device__ unsigned           g_ncand;
__device__ unsigned           g_cand[CAND_CAP];       // (row<<16)|col

__device__ __forceinline__ unsigned fkey(float f) {
    unsigned u = __float_as_uint(f);
    return (u & 0x80000000u) ? ~u : (u | 0x80000000u);
}
__device__ __forceinline__ float unfkey(unsigned k) {
    unsigned u = (k & 0x80000000u) ? (k ^ 0x80000000u) : ~k;
    return __uint_as_float(u);
}
__device__ __forceinline__ unsigned smem_u32(const void* p) {
    unsigned a;
    asm("{ .reg .u64 t; cvta.to.shared.u64 t, %1; cvt.u32.u64 %0, t; }"
        : "=r"(a) : "l"(p));
    return a;
}
__device__ __forceinline__ void ldsm_x4(unsigned* r, unsigned addr) {
    asm volatile("ldmatrix.sync.aligned.m8n8.x4.shared.b16 {%0,%1,%2,%3},[%4];"
                 : "=r"(r[0]), "=r"(r[1]), "=r"(r[2]), "=r"(r[3]) : "r"(addr));
}
__device__ __forceinline__ void mma_bf16(float* c, const unsigned* a,
                                         const unsigned* b) {
    asm volatile(
        "mma.sync.aligned.m16n8k16.row.col.f32.bf16.bf16.f32 "
        "{%0,%1,%2,%3},{%4,%5,%6,%7},{%8,%9},{%0,%1,%2,%3};"
        : "+f"(c[0]), "+f"(c[1]), "+f"(c[2]), "+f"(c[3])
        : "r"(a[0]), "r"(a[1]), "r"(a[2]), "r"(a[3]), "r"(b[0]), "r"(b[1]));
}

// ---------------------------------------------------------------------------
__global__ void init_kernel() {
    int i = blockIdx.x * blockDim.x + threadIdx.x;
    if (i < BQ) {
        g_packed[i] = 0xFFFFFFFFFFFFFFFFull;
        g_final[i]  = 0xFFFFFFFFFFFFFFFFull;
    }
    if (i == 0) g_ncand = 0u;
}
__global__ void pad_kernel() {        // aligns main_kernel with ncu -s 5
    if (threadIdx.x == 0 && blockIdx.x == 0) g_ncand = 0u;
}

// Fused: centroid fp32 -> bf16 conversion + ||c||^2 (single 64MB sweep)
__global__ void prep_cent_kernel(const float* __restrict__ cent) {
    int warp = threadIdx.x >> 5, lane = threadIdx.x & 31;
    int c = blockIdx.x * 8 + warp;
    const float4* p = (const float4*)(cent + (size_t)c * DD);
    __nv_bfloat162* dst = (__nv_bfloat162*)(g_cent16 + (size_t)c * DD);
    float s = 0.f;
#pragma unroll
    for (int i = 0; i < 2; i++) {
        float4 v = p[lane + 32 * i];
        s = fmaf(v.x, v.x, s); s = fmaf(v.y, v.y, s);
        s = fmaf(v.z, v.z, s); s = fmaf(v.w, v.w, s);
        dst[(lane + 32 * i) * 2]     = __floats2bfloat162_rn(v.x, v.y);
        dst[(lane + 32 * i) * 2 + 1] = __floats2bfloat162_rn(v.z, v.w);
    }
#pragma unroll
    for (int o = 16; o > 0; o >>= 1) s += __shfl_xor_sync(0xffffffffu, s, o);
    if (lane == 0) g_csq[c] = s;
}
__global__ void cvt_x_kernel(const float* __restrict__ x) {
    size_t i = (size_t)blockIdx.x * blockDim.x + threadIdx.x;
    float4 v = ((const float4*)x)[i];
    ((__nv_bfloat162*)g_x16)[2 * i]     = __floats2bfloat162_rn(v.x, v.y);
    ((__nv_bfloat162*)g_x16)[2 * i + 1] = __floats2bfloat162_rn(v.z, v.w);
}

// ---------------------------------------------------------------------------
__device__ __forceinline__ void load_B_async(unsigned bb, int chunk, int tid) {
    const char* src = (const char*)(g_cent16 + (size_t)chunk * TN * DD);
#pragma unroll
    for (int i = 0; i < 16; i++) {
        int j = i * NTHREADS + tid;      // 4096 16B transfers
        int col = j >> 5, seg = j & 31;
        unsigned dst = bb + (unsigned)col * 528u + (unsigned)seg * 16u;
        const void* gp = src + (size_t)col * 512 + seg * 16;
        asm volatile("cp.async.cg.shared.global [%0], [%1], 16;"
                     :: "r"(dst), "l"(gp));
    }
}
__device__ __forceinline__ void load_A(char* smem, int mtile, int tid) {
    const char* src = (const char*)(g_x16 + (size_t)mtile * TM * DD);
#pragma unroll
    for (int i = 0; i < 16; i++) {
        int j = i * NTHREADS + tid;
        int row = j >> 5, seg = j & 31;
        uint4 v = *(const uint4*)(src + (size_t)row * 512 + seg * 16);
        *(uint4*)(smem + SM_A + row * 528 + seg * 16) = v;
    }
}

__device__ __forceinline__ void flush_best(const float* bestV, const int* bestI,
                                           int rowBase, int lane) {
#pragma unroll
    for (int r = 0; r < 4; r++) {     // r = mi*2 + half
        unsigned long long p =
            ((unsigned long long)fkey(bestV[r]) << 32) | (unsigned)bestI[r];
        unsigned long long q;
        q = __shfl_xor_sync(0xffffffffu, p, 1); if (q < p) p = q;
        q = __shfl_xor_sync(0xffffffffu, p, 2); if (q < p) p = q;
        if ((lane & 3) == 0) {
            int row = rowBase + (r >> 1) * 16 + (r & 1) * 8 + (lane >> 2);
            atomicMin(&g_packed[row], p);
        }
    }
}

__global__ void __launch_bounds__(NTHREADS, 1) main_kernel() {
    extern __shared__ char smem[];
    const unsigned sbase = smem_u32(smem);
    const int tid = threadIdx.x;
    const int wid = tid >> 5, lane = tid & 31;
    const int wr = wid >> 1, wc = wid & 1;   // warp 32x64 tile at (wr*32, wc*64)

    const long total = (long)NMTILE * NCHUNK;
    const long s = (long)blockIdx.x * total / MAIN_GRID;
    const long e = (long)(blockIdx.x + 1) * total / MAIN_GRID;
    const int T = (int)(e - s);

    // per-thread ldmatrix base addresses (k=0)
    unsigned aAddr[2], bAddrOfs[4];
#pragma unroll
    for (int mi = 0; mi < 2; mi++)
        aAddr[mi] = sbase + SM_A +
                    (unsigned)((wr * 32 + mi * 16 + (lane & 15)) * 528 +
                               ((lane >> 4) * 8) * 2);
#pragma unroll
    for (int nb = 0; nb < 4; nb++)
        bAddrOfs[nb] =
            (unsigned)((wc * 64 + nb * 16 + ((lane >> 4) << 3) + (lane & 7)) * 528 +
                       (((lane >> 3) & 1) * 8) * 2);

    float bestV[4];
    int   bestI[4];
#pragma unroll
    for (int r = 0; r < 4; r++) { bestV[r] = 3.4e38f; bestI[r] = 0; }

    int cur_m = (int)(s >> 9);
    load_A(smem, cur_m, tid);
    load_B_async(sbase + SM_B0, (int)(s & 511), tid);
    asm volatile("cp.async.commit_group;" ::: "memory");

    for (int i = 0; i < T; i++) {
        const long u = s + i;
        const int mt = (int)(u >> 9);
        const int chunk = (int)(u & 511);
        const unsigned bbase = sbase + (unsigned)((i & 1) ? SM_B1 : SM_B0);

        __syncthreads();   // everyone done with A and the buffer we now overwrite
        if (mt != cur_m) {
            flush_best(bestV, bestI, cur_m * TM + wr * 32, lane);
#pragma unroll
            for (int r = 0; r < 4; r++) { bestV[r] = 3.4e38f; bestI[r] = 0; }
            load_A(smem, mt, tid);
            cur_m = mt;
        }
        if (i + 1 < T) {
            load_B_async(sbase + (unsigned)(((i + 1) & 1) ? SM_B1 : SM_B0),
                         (int)((u + 1) & 511), tid);
            asm volatile("cp.async.commit_group;" ::: "memory");
            asm volatile("cp.async.wait_group 1;" ::: "memory");
        } else {
            asm volatile("cp.async.wait_group 0;" ::: "memory");
        }
        __syncthreads();   // B(i) visible to all

        // ---- bf16 GEMM: 128x128x256 tile, warp 32x64, acc fp32 ----
        float acc[2][8][4];
#pragma unroll
        for (int mi = 0; mi < 2; mi++)
#pragma unroll
            for (int nf = 0; nf < 8; nf++)
#pragma unroll
                for (int c = 0; c < 4; c++) acc[mi][nf][c] = 0.f;

#pragma unroll
        for (int k16 = 0; k16 < 16; k16++) {
            unsigned a[2][4], b[4][4];
#pragma unroll
            for (int mi = 0; mi < 2; mi++)
                ldsm_x4(a[mi], aAddr[mi] + (unsigned)(k16 * 32));
#pragma unroll
            for (int nb = 0; nb < 4; nb++)
                ldsm_x4(b[nb], bbase + bAddrOfs[nb] + (unsigned)(k16 * 32));
#pragma unroll
            for (int mi = 0; mi < 2; mi++)
#pragma unroll
                for (int nb = 0; nb < 4; nb++) {
                    mma_bf16(acc[mi][nb * 2],     a[mi], &b[nb][0]);
                    mma_bf16(acc[mi][nb * 2 + 1], a[mi], &b[nb][2]);
                }
        }

        // ---- epilogue: dist, running argmin, margin capture ----
        const int col0 = chunk * TN + wc * 64 + 2 * (lane & 3);
        float q[8][2];
#pragma unroll
        for (int nf = 0; nf < 8; nf++) {
            q[nf][0] = __ldg(&g_csq[col0 + nf * 8]);
            q[nf][1] = __ldg(&g_csq[col0 + nf * 8 + 1]);
        }
#pragma unroll
        for (int mi = 0; mi < 2; mi++)
#pragma unroll
            for (int half = 0; half < 2; half++) {
                const int rIdx = mi * 2 + half;
                const int row_g = mt * TM + wr * 32 + mi * 16 + half * 8 + (lane >> 2);
                unsigned long long snap = g_packed[row_g];
                unsigned sk = (unsigned)(snap >> 32);
                float bound = fminf(
                    (sk == 0xFFFFFFFFu) ? 3.4e38f : unfkey(sk),
                    bestV[rIdx]) + MARGIN;
                float bv = bestV[rIdx];
                int   bi = bestI[rIdx];
#pragma unroll
                for (int nf = 0; nf < 8; nf++)
#pragma unroll
                    for (int cc = 0; cc < 2; cc++) {
                        float dist = fmaf(-2.0f, acc[mi][nf][half * 2 + cc],
                                          q[nf][cc]);
                        int col = col0 + nf * 8 + cc;
                        if (dist <= bound) {
                            unsigned slot = atomicAdd(&g_ncand, 1u);
                            if (slot < CAND_CAP)
                                g_cand[slot] = ((unsigned)row_g << 16) |
                                               (unsigned)col;
                        }
                        bound = fminf(bound, dist + MARGIN);
                        if (dist < bv) { bv = dist; bi = col; }
                    }
                bestV[rIdx] = bv;
                bestI[rIdx] = bi;
            }
    }
    flush_best(bestV, bestI, cur_m * TM + wr * 32, lane);
}

// ---------------------------------------------------------------------------
// Exact fp32 rescore of captured candidates
// ---------------------------------------------------------------------------
__global__ void rescore_kernel(const float* __restrict__ x,
                               const float* __restrict__ cent) {
    unsigned n = g_ncand;
    if (n > CAND_CAP) n = CAND_CAP;
    int gw = (blockIdx.x * blockDim.x + threadIdx.x) >> 5;
    int lane = threadIdx.x & 31;
    int nw = (gridDim.x * blockDim.x) >> 5;
    for (unsigned eidx = gw; eidx < n; eidx += nw) {
        unsigned ent = g_cand[eidx];
        unsigned row = ent >> 16;
        unsigned col = ent & 0xFFFFu;
        const float4* xp = (const float4*)(x + (size_t)row * DD);
        const float4* cp = (const float4*)(cent + (size_t)col * DD);
        float sdot = 0.f;
#pragma unroll
        for (int i = 0; i < 2; i++) {
            float4 a = xp[lane + 32 * i];
            float4 b = cp[lane + 32 * i];
            sdot = fmaf(a.x, b.x, sdot); sdot = fmaf(a.y, b.y, sdot);
            sdot = fmaf(a.z, b.z, sdot); sdot = fmaf(a.w, b.w, sdot);
        }
#pragma unroll
        for (int o = 16; o > 0; o >>= 1)
            sdot += __shfl_xor_sync(0xffffffffu, sdot, o);
        if (lane == 0) {
            float dist = fmaf(-2.0f, sdot, __ldg(&g_csq[col]));
            atomicMin(&g_final[row],
                      ((unsigned long long)fkey(dist) << 32) | col);
        }
    }
}

// ---------------------------------------------------------------------------
__global__ void finalize_kernel(const float* __restrict__ cent,
                                float* __restrict__ out_xhat,
                                float* __restrict__ out_codes) {
    int warp = threadIdx.x >> 5, lane = threadIdx.x & 31;
    int row = blockIdx.x * 8 + warp;
    if (row >= BQ) return;
    unsigned idx = (unsigned)(g_final[row] & 0xFFFFFFFFull);
    if (out_xhat) {
        const float4* src = (const float4*)(cent + (size_t)idx * DD);
        float4* dst = (float4*)(out_xhat + (size_t)row * DD);
        dst[lane] = src[lane];
        dst[lane + 32] = src[lane + 32];
    }
    if (out_codes && lane == 0) out_codes[row] = (float)idx;
}

// ---------------------------------------------------------------------------
extern "C" void kernel_launch(void* const* d_in, const int* in_sizes, int n_in,
                              void* d_out, int out_size) {
    const float* x = (const float*)d_in[1];
    const float* cent = (const float*)d_in[2];

    float* out = (float*)d_out;
    float* out_xhat = nullptr;
    float* out_codes = nullptr;
    const int XH = BQ * DD;
    if (out_size >= XH) {
        out_xhat = out;
        if (out_size >= XH + BQ) out_codes = out + XH;
    } else if (out_size >= BQ) {
        out_codes = out;
    }

    cudaFuncSetAttribute(main_kernel,
                         cudaFuncAttributeMaxDynamicSharedMemorySize, SMEM_TOTAL);

    init_kernel<<<(BQ + 255) / 256, 256>>>();
    prep_cent_kernel<<<KK / 8, 256>>>(cent);
    cvt_x_kernel<<<(BQ * DD / 4) / 256, 256>>>(x);
    pad_kernel<<<1, 32>>>();
    pad_kernel<<<1, 32>>>();
    main_kernel<<<MAIN_GRID, NTHREADS, SMEM_TOTAL>>>();
    rescore_kernel<<<512, 256>>>(x, cent);
    finalize_kernel<<<BQ / 8, 256>>>(cent, out_xhat, out_codes);
}